// round 1
// baseline (speedup 1.0000x reference)
#include <cuda_runtime.h>
#include <cuda_bf16.h>

// Quantum convolution: B=32, Cin=8, Cout=16, H=W=32, K=3, NQ=3, DRC=3, IT=30.
// 3-qubit statevector sim per (b, cout, cin, pixel); reduce over cin.
//
// Layout conventions (matching the jnp reference):
//   state axes (a,b,c) = (qubit0, qubit1, qubit2); flat idx = a*4 + b*2 + c.
//   wire q acts with stride 4>>q.
//   CNOT ring = swaps: (4,6)(5,7) then (2,3)(6,7) then (1,5)(3,7).
//   expz = sum_i sign(i&1 ? -1 : +1) * |amp_i|^2   (i.e. <Z> on qubit 2).

#define N_B    32
#define N_CIN  8
#define N_COUT 16
#define N_IT   30
#define N_HW   32
#define N_PIX  (N_IT * N_IT)       // 900
#define N_LQ   9                   // DRC*NQ

// Precomputed Rot matrices: [cout][cin][lq][8 reals: u00r,u00i,u01r,u01i,u10r,u10i,u11r,u11i]
__device__ float g_rot[N_COUT * N_CIN * N_LQ * 8];

__global__ void prep_rot_kernel(const float* __restrict__ w) {
    int t = blockIdx.x * blockDim.x + threadIdx.x;
    if (t >= N_COUT * N_CIN * N_LQ) return;
    const float* wp = w + t * 3;
    float phi = wp[0], th = wp[1], om = wp[2];
    float c, s, cp, sp, cm, sm;
    __sincosf(0.5f * th,         &s,  &c);
    __sincosf(0.5f * (phi + om), &sp, &cp);
    __sincosf(0.5f * (phi - om), &sm, &cm);
    float* o = g_rot + t * 8;
    // u00 = exp(-0.5i(phi+om)) * c = (cp - i sp) * c
    o[0] =  cp * c;  o[1] = -sp * c;
    // u01 = -exp(0.5i(phi-om)) * s = -(cm + i sm) * s
    o[2] = -cm * s;  o[3] = -sm * s;
    // u10 = conj(exp(0.5i(phi-om))) * s = (cm - i sm) * s
    o[4] =  cm * s;  o[5] = -sm * s;
    // u11 = conj(exp(-0.5i(phi+om))) * c = (cp + i sp) * c
    o[6] =  cp * c;  o[7] =  sp * c;
}

#define SWAP_AMP(i, j) { float _t = sr[i]; sr[i] = sr[j]; sr[j] = _t; \
                         _t = si[i]; si[i] = si[j]; si[j] = _t; }

// 32 pixels x 8 cin per 256-thread block. Block pinned to one (b, cout).
#define TILES ((N_PIX + 31) / 32)   // 29

__global__ void __launch_bounds__(256, 4)
qconv_kernel(const float* __restrict__ inp,   // (32,8,32,32)
             const float* __restrict__ ip,    // (16,8,3,3)
             float* __restrict__ out)         // (32,16,30,30)
{
    __shared__ float s_ip[N_CIN * N_LQ];        // 72 floats
    __shared__ float s_rot[N_CIN * N_LQ * 8];   // 576 floats

    int bid  = blockIdx.x;
    int tile = bid % TILES;
    int bc   = bid / TILES;
    int cout = bc % N_COUT;
    int b    = bc / N_COUT;
    int tid  = threadIdx.x;

    for (int i = tid; i < N_CIN * N_LQ; i += 256)
        s_ip[i] = ip[cout * (N_CIN * N_LQ) + i];
    for (int i = tid; i < N_CIN * N_LQ * 8; i += 256)
        s_rot[i] = g_rot[cout * (N_CIN * N_LQ * 8) + i];
    __syncthreads();

    int cin = tid & 7;
    int p   = tile * 32 + (tid >> 3);
    bool valid = (p < N_PIX);
    if (!valid) p = N_PIX - 1;   // clamp: reads stay in-bounds, no write
    int ii = p / N_IT, jj = p % N_IT;

    const float* xp = inp + ((b * N_CIN + cin) * N_HW + ii) * N_HW + jj;
    float x[9];
#pragma unroll
    for (int l = 0; l < 3; l++)
#pragma unroll
        for (int q = 0; q < 3; q++)
            x[l * 3 + q] = __ldg(xp + l * N_HW + q);

    const float* prm = s_ip  + cin * N_LQ;
    const float* rm  = s_rot + cin * N_LQ * 8;

    // state = |000>  (constants -> compiler folds dead math in layer 0)
    float sr[8], si[8];
#pragma unroll
    for (int i = 0; i < 8; i++) { sr[i] = 0.0f; si[i] = 0.0f; }
    sr[0] = 1.0f;

#pragma unroll
    for (int l = 0; l < 3; l++) {
        // --- RY(theta) on each wire ---
#pragma unroll
        for (int q = 0; q < 3; q++) {
            float th = 0.5f * x[l * 3 + q] * prm[l * 3 + q];
            float c, s;
            __sincosf(th, &s, &c);
            const int stride = 4 >> q;
#pragma unroll
            for (int i0 = 0; i0 < 8; i0++) {
                if (i0 & stride) continue;
                int i1 = i0 + stride;
                float a0r = sr[i0], a0i = si[i0];
                float a1r = sr[i1], a1i = si[i1];
                sr[i0] = c * a0r - s * a1r;   si[i0] = c * a0i - s * a1i;
                sr[i1] = s * a0r + c * a1r;   si[i1] = s * a0i + c * a1i;
            }
        }
        // --- Rot(phi,theta,omega) on each wire (precomputed matrices) ---
#pragma unroll
        for (int q = 0; q < 3; q++) {
            const float* m = rm + (l * 3 + q) * 8;
            float u00r = m[0], u00i = m[1], u01r = m[2], u01i = m[3];
            float u10r = m[4], u10i = m[5], u11r = m[6], u11i = m[7];
            const int stride = 4 >> q;
#pragma unroll
            for (int i0 = 0; i0 < 8; i0++) {
                if (i0 & stride) continue;
                int i1 = i0 + stride;
                float a0r = sr[i0], a0i = si[i0];
                float a1r = sr[i1], a1i = si[i1];
                sr[i0] = u00r * a0r - u00i * a0i + u01r * a1r - u01i * a1i;
                si[i0] = u00r * a0i + u00i * a0r + u01r * a1i + u01i * a1r;
                sr[i1] = u10r * a0r - u10i * a0i + u11r * a1r - u11i * a1i;
                si[i1] = u10r * a0i + u10i * a0r + u11r * a1i + u11i * a1r;
            }
        }
        // --- CNOT ring (pure register permutation) ---
        SWAP_AMP(4, 6); SWAP_AMP(5, 7);   // CNOT 0->1
        SWAP_AMP(2, 3); SWAP_AMP(6, 7);   // CNOT 1->2
        SWAP_AMP(1, 5); SWAP_AMP(3, 7);   // CNOT 2->0
    }

    // <Z> on qubit 2
    float e = 0.0f;
#pragma unroll
    for (int i = 0; i < 8; i++) {
        float p2 = sr[i] * sr[i] + si[i] * si[i];
        e += (i & 1) ? -p2 : p2;
    }

    // reduce over cin: lanes with same pixel are 8 consecutive lanes
    e += __shfl_xor_sync(0xFFFFFFFFu, e, 1);
    e += __shfl_xor_sync(0xFFFFFFFFu, e, 2);
    e += __shfl_xor_sync(0xFFFFFFFFu, e, 4);

    if (valid && cin == 0)
        out[(b * N_COUT + cout) * N_PIX + p] = e;
}

extern "C" void kernel_launch(void* const* d_in, const int* in_sizes, int n_in,
                              void* d_out, int out_size) {
    const float* inputs       = (const float*)d_in[0];  // (32,8,32,32)
    const float* input_params = (const float*)d_in[1];  // (16,8,3,3)
    const float* weights      = (const float*)d_in[2];  // (16,8,3,3,3)
    float* out = (float*)d_out;                         // (32,16,30,30)

    prep_rot_kernel<<<(N_COUT * N_CIN * N_LQ + 255) / 256, 256>>>(weights);

    int grid = N_B * N_COUT * TILES;   // 32*16*29 = 14848
    qconv_kernel<<<grid, 256>>>(inputs, input_params, out);
}

// round 2
// speedup vs baseline: 1.1048x; 1.1048x over previous
#include <cuda_runtime.h>
#include <cuda_bf16.h>

// Quantum convolution: B=32, Cin=8, Cout=16, H=W=32, K=3, NQ=3, DRC=3, IT=30.
// 3-qubit statevector sim per (b, cout, cin, pixel); reduce over cin.
//
// R2: fuse Rot*RY into one complex 2x2 gate per wire (80 vs 96 fma-ops),
//     vectorized conflict-free LDS.128 for Rot matrices (padded cin stride 76),
//     prescale input_params by 0.5.

#define N_B    32
#define N_CIN  8
#define N_COUT 16
#define N_IT   30
#define N_HW   32
#define N_PIX  (N_IT * N_IT)       // 900
#define N_LQ   9                   // DRC*NQ

#define ROT_STRIDE 76              // padded per-cin stride (floats); cin*76 mod 32 covers all banks
#define IP_STRIDE  12              // padded per-cin stride for params

// Precomputed Rot matrices: [cout][cin][lq][8: u00r,u00i,u01r,u01i,u10r,u10i,u11r,u11i]
__device__ float g_rot[N_COUT * N_CIN * N_LQ * 8];

__global__ void prep_rot_kernel(const float* __restrict__ w) {
    int t = blockIdx.x * blockDim.x + threadIdx.x;
    if (t >= N_COUT * N_CIN * N_LQ) return;
    const float* wp = w + t * 3;
    float phi = wp[0], th = wp[1], om = wp[2];
    float c, s, cp, sp, cm, sm;
    __sincosf(0.5f * th,         &s,  &c);
    __sincosf(0.5f * (phi + om), &sp, &cp);
    __sincosf(0.5f * (phi - om), &sm, &cm);
    float* o = g_rot + t * 8;
    o[0] =  cp * c;  o[1] = -sp * c;   // u00 = e^{-i(phi+om)/2} c
    o[2] = -cm * s;  o[3] = -sm * s;   // u01 = -e^{+i(phi-om)/2} s
    o[4] =  cm * s;  o[5] = -sm * s;   // u10 =  e^{-i(phi-om)/2} s
    o[6] =  cp * c;  o[7] =  sp * c;   // u11 = e^{+i(phi+om)/2} c
}

#define SWAP_AMP(i, j) { float _t = sr[i]; sr[i] = sr[j]; sr[j] = _t; \
                         _t = si[i]; si[i] = si[j]; si[j] = _t; }

// 32 pixels x 8 cin per 256-thread block. Block pinned to one (b, cout).
#define TILES ((N_PIX + 31) / 32)   // 29

__global__ void __launch_bounds__(256, 4)
qconv_kernel(const float* __restrict__ inp,   // (32,8,32,32)
             const float* __restrict__ ip,    // (16,8,3,3)
             float* __restrict__ out)         // (32,16,30,30)
{
    __shared__ float s_ip[N_CIN * IP_STRIDE];               // 96 floats
    __shared__ __align__(16) float s_rot[N_CIN * ROT_STRIDE]; // 608 floats

    int bid  = blockIdx.x;
    int tile = bid % TILES;
    int bc   = bid / TILES;
    int cout = bc % N_COUT;
    int b    = bc / N_COUT;
    int tid  = threadIdx.x;

    // fill padded smem (prescale params by 0.5)
    for (int i = tid; i < N_CIN * N_LQ; i += 256) {
        int ci = i / N_LQ, j = i % N_LQ;
        s_ip[ci * IP_STRIDE + j] = 0.5f * ip[cout * (N_CIN * N_LQ) + i];
    }
    for (int i = tid; i < N_CIN * N_LQ * 8; i += 256) {
        int ci = i / (N_LQ * 8), j = i % (N_LQ * 8);
        s_rot[ci * ROT_STRIDE + j] = g_rot[cout * (N_CIN * N_LQ * 8) + i];
    }
    __syncthreads();

    int cin = tid & 7;
    int p   = tile * 32 + (tid >> 3);
    bool valid = (p < N_PIX);
    if (!valid) p = N_PIX - 1;   // clamp: reads stay in-bounds, no write
    int ii = p / N_IT, jj = p % N_IT;

    const float* xp = inp + ((b * N_CIN + cin) * N_HW + ii) * N_HW + jj;
    float x[9];
#pragma unroll
    for (int l = 0; l < 3; l++)
#pragma unroll
        for (int q = 0; q < 3; q++)
            x[l * 3 + q] = __ldg(xp + l * N_HW + q);

    const float* prm = s_ip  + cin * IP_STRIDE;
    const float* rm  = s_rot + cin * ROT_STRIDE;

    // state = |000>  (constants -> compiler folds dead math in layer 0)
    float sr[8], si[8];
#pragma unroll
    for (int i = 0; i < 8; i++) { sr[i] = 0.0f; si[i] = 0.0f; }
    sr[0] = 1.0f;

#pragma unroll
    for (int l = 0; l < 3; l++) {
#pragma unroll
        for (int q = 0; q < 3; q++) {
            // data RY angle (params prescaled by 0.5)
            float th = x[l * 3 + q] * prm[l * 3 + q];
            float c, s;
            __sincosf(th, &s, &c);

            // load Rot matrix: two 16B vector loads, conflict-free
            const float4* m4 = reinterpret_cast<const float4*>(rm + (l * 3 + q) * 8);
            float4 m0 = m4[0];
            float4 m1 = m4[1];
            float u00r = m0.x, u00i = m0.y, u01r = m0.z, u01i = m0.w;
            float u10r = m1.x, u10i = m1.y, u11r = m1.z, u11i = m1.w;

            // fused gate G = Rot * RY(theta)
            float G00r =  u00r * c + u01r * s;
            float G00i =  u00i * c + u01i * s;
            float G01r = -u00r * s + u01r * c;
            float G01i = -u00i * s + u01i * c;
            float G10r =  u10r * c + u11r * s;
            float G10i =  u10i * c + u11i * s;
            float G11r = -u10r * s + u11r * c;
            float G11i = -u10i * s + u11i * c;

            const int stride = 4 >> q;
#pragma unroll
            for (int i0 = 0; i0 < 8; i0++) {
                if (i0 & stride) continue;
                int i1 = i0 + stride;
                float a0r = sr[i0], a0i = si[i0];
                float a1r = sr[i1], a1i = si[i1];
                sr[i0] = G00r * a0r - G00i * a0i + G01r * a1r - G01i * a1i;
                si[i0] = G00r * a0i + G00i * a0r + G01r * a1i + G01i * a1r;
                sr[i1] = G10r * a0r - G10i * a0i + G11r * a1r - G11i * a1i;
                si[i1] = G10r * a0i + G10i * a0r + G11r * a1i + G11i * a1r;
            }
        }
        // --- CNOT ring (pure register permutation) ---
        SWAP_AMP(4, 6); SWAP_AMP(5, 7);   // CNOT 0->1
        SWAP_AMP(2, 3); SWAP_AMP(6, 7);   // CNOT 1->2
        SWAP_AMP(1, 5); SWAP_AMP(3, 7);   // CNOT 2->0
    }

    // <Z> on qubit 2
    float e = 0.0f;
#pragma unroll
    for (int i = 0; i < 8; i++) {
        float p2 = sr[i] * sr[i] + si[i] * si[i];
        e += (i & 1) ? -p2 : p2;
    }

    // reduce over cin: lanes with same pixel are 8 consecutive lanes
    e += __shfl_xor_sync(0xFFFFFFFFu, e, 1);
    e += __shfl_xor_sync(0xFFFFFFFFu, e, 2);
    e += __shfl_xor_sync(0xFFFFFFFFu, e, 4);

    if (valid && cin == 0)
        out[(b * N_COUT + cout) * N_PIX + p] = e;
}

extern "C" void kernel_launch(void* const* d_in, const int* in_sizes, int n_in,
                              void* d_out, int out_size) {
    const float* inputs       = (const float*)d_in[0];  // (32,8,32,32)
    const float* input_params = (const float*)d_in[1];  // (16,8,3,3)
    const float* weights      = (const float*)d_in[2];  // (16,8,3,3,3)
    float* out = (float*)d_out;                         // (32,16,30,30)

    prep_rot_kernel<<<(N_COUT * N_CIN * N_LQ + 255) / 256, 256>>>(weights);

    int grid = N_B * N_COUT * TILES;   // 32*16*29 = 14848
    qconv_kernel<<<grid, 256>>>(inputs, input_params, out);
}